// round 9
// baseline (speedup 1.0000x reference)
#include <cuda_runtime.h>
#include <cstdint>

// Scratch (module-scope device globals; no runtime allocation)
__device__ float g_y[576LL * 262144];    // qkv-linear output, [o][b][pos]
__device__ float g_att[192LL * 262144];  // attention output,  [c][b][pos]

// ---------------------------------------------------------------------------
__device__ __forceinline__ uint32_t smem_u32(const void* p) {
  uint32_t a;
  asm("{ .reg .u64 t; cvta.to.shared.u64 t, %1; cvt.u32.u64 %0, t; }"
      : "=r"(a) : "l"(p));
  return a;
}
#define CPA16(dst, src, sz) \
  asm volatile("cp.async.cg.shared.global [%0], [%1], 16, %2;" ::"r"(dst), "l"(src), "r"(sz))
#define CPA_COMMIT() asm volatile("cp.async.commit_group;")
#define CPA_WAIT(n) asm volatile("cp.async.wait_group %0;" ::"n"(n) : "memory")

__device__ __forceinline__ uint32_t f2tf(float f) {
  uint32_t u;
  asm("cvt.rna.tf32.f32 %0, %1;" : "=r"(u) : "f"(f));
  return u;
}
__device__ __forceinline__ void mma8(float* d, const uint32_t* a,
                                     const uint32_t* b) {
  asm volatile(
      "mma.sync.aligned.m16n8k8.row.col.f32.tf32.tf32.f32 "
      "{%0,%1,%2,%3},{%4,%5,%6,%7},{%8,%9},{%0,%1,%2,%3};"
      : "+f"(d[0]), "+f"(d[1]), "+f"(d[2]), "+f"(d[3])
      : "r"(a[0]), "r"(a[1]), "r"(a[2]), "r"(a[3]), "r"(b[0]), "r"(b[1]));
}

// ---------------------------------------------------------------------------
// Out[m, n] = sum_k W[m,k] * In[k, n],  n = b*65536 + pos (N-tile within one b)
// CTA tile 128x128, K=192 (12 chunks of 16, double-buffered cp.async).
// ---------------------------------------------------------------------------
__global__ void __launch_bounds__(256, 2) gemm_mma(
    const float* __restrict__ W, const float* __restrict__ In,
    float* __restrict__ Out, int Mvalid, long long ch_str, long long b_str,
    long long o_str, long long ob_str) {
  __shared__ __align__(16) float As[2][128 * 20];
  __shared__ __align__(16) float Bs[2][16 * 136];

  const int tid = threadIdx.x;
  const int warp = tid >> 5, lane = tid & 31, gid = lane >> 2, tig = lane & 3;
  const int wm = warp & 1, wn = warp >> 1;
  const int m0 = blockIdx.y << 7;
  const int n0 = blockIdx.x << 7;
  const int bb = n0 >> 16, pos0 = n0 & 65535;
  const float* inb = In + bb * b_str + pos0;
  const uint32_t sA = smem_u32(As), sB = smem_u32(Bs);

  float acc[4][4][4];
#pragma unroll
  for (int i = 0; i < 4; ++i)
#pragma unroll
    for (int j = 0; j < 4; ++j)
#pragma unroll
      for (int q = 0; q < 4; ++q) acc[i][j][q] = 0.f;

  auto loadA = [&](int buf, int kc) {
#pragma unroll
    for (int t = 0; t < 2; ++t) {
      int idx = (t << 8) + tid;
      int r = idx >> 2, q = idx & 3;
      int m = m0 + r;
      int valid = m < Mvalid;
      const float* src = W + (long long)(valid ? m : 0) * 192 + kc + (q << 2);
      uint32_t dst = sA + (uint32_t)(buf * 2560 + r * 20 + q * 4) * 4;
      CPA16(dst, src, valid ? 16 : 0);
    }
  };
  auto loadB = [&](int buf, int kc) {
#pragma unroll
    for (int t = 0; t < 2; ++t) {
      int idx = (t << 8) + tid;
      int r = idx >> 5, q = idx & 31;
      const float* src = inb + (long long)(kc + r) * ch_str + (q << 2);
      uint32_t dst = sB + (uint32_t)(buf * 2176 + r * 136 + q * 4) * 4;
      CPA16(dst, src, 16);
    }
  };

  auto compute = [&](int buf) {
    const float* A = As[buf];
    const float* B = Bs[buf];
#pragma unroll
    for (int kb = 0; kb < 2; ++kb) {
      const int kk = kb * 8;
      uint32_t af[4][4];
#pragma unroll
      for (int mf = 0; mf < 4; ++mf) {
        const float* ap = A + (wm * 64 + mf * 16 + gid) * 20 + kk + tig;
        af[mf][0] = f2tf(ap[0]);
        af[mf][1] = f2tf(ap[160]);
        af[mf][2] = f2tf(ap[4]);
        af[mf][3] = f2tf(ap[164]);
      }
      uint32_t bf[4][2];
#pragma unroll
      for (int nf = 0; nf < 4; ++nf) {
        const float* bp = B + (kk + tig) * 136 + wn * 32 + nf * 8 + gid;
        bf[nf][0] = f2tf(bp[0]);
        bf[nf][1] = f2tf(bp[544]);
      }
#pragma unroll
      for (int mf = 0; mf < 4; ++mf)
#pragma unroll
        for (int nf = 0; nf < 4; ++nf) mma8(acc[mf][nf], af[mf], bf[nf]);
    }
  };

  loadA(0, 0);
  loadB(0, 0);
  CPA_COMMIT();
#pragma unroll 1
  for (int i = 0; i < 12; ++i) {
    if (i + 1 < 12) {
      loadA((i + 1) & 1, (i + 1) * 16);
      loadB((i + 1) & 1, (i + 1) * 16);
      CPA_COMMIT();
      CPA_WAIT(1);
    } else {
      CPA_WAIT(0);
    }
    __syncthreads();
    compute(i & 1);
    __syncthreads();
  }

  // Epilogue: float2 stores (full 32B sectors per 4 consecutive lanes)
#pragma unroll
  for (int mf = 0; mf < 4; ++mf) {
    int mA = m0 + wm * 64 + mf * 16 + gid;
    int mB = mA + 8;
#pragma unroll
    for (int nf = 0; nf < 4; ++nf) {
      int c = pos0 + wn * 32 + nf * 8 + 2 * tig;
      if (mA < Mvalid)
        *(float2*)(Out + (long long)mA * o_str + bb * ob_str + c) =
            make_float2(acc[mf][nf][0], acc[mf][nf][1]);
      if (mB < Mvalid)
        *(float2*)(Out + (long long)mB * o_str + bb * ob_str + c) =
            make_float2(acc[mf][nf][2], acc[mf][nf][3]);
    }
  }
}

// ---------------------------------------------------------------------------
// k2: per (window, head): gather (roll + window) from g_y, depthwise 3x3
// (thirds processed sequentially), L2-norm channel attention, scatter to
// g_att in natural layout (inverse roll).
// ---------------------------------------------------------------------------
__global__ void __launch_bounds__(256) k2_dw_attn(
    const float* __restrict__ dw_w, const float* __restrict__ temp) {
  __shared__ __align__(16) float pre[32 * 64];
  __shared__ __align__(16) float qs[32 * 68];
  __shared__ __align__(16) float ks[32 * 68];
  __shared__ __align__(16) float vs[32 * 64];
  __shared__ float attn[32 * 33];
  __shared__ float qsc[32], ksc[32];
  float* wsm = attn;  // 288 dw weights staged here before logits phase

  const int tid = threadIdx.x, win = blockIdx.x, head = blockIdx.y;
  const int b = win >> 10, wy = (win >> 5) & 31, wx = win & 31;
  const int hb = wy * 8 + 4, wb = wx * 8 + 4;

#pragma unroll 1
  for (int t3 = 0; t3 < 3; ++t3) {
    // Gather 32 channels x 64 positions (rolled window) from g_y
    {
      int c = tid >> 3, i = tid & 7;
      int cg = t3 * 192 + head * 32 + c;
      const float* src =
          g_y + (long long)cg * 262144 + b * 65536 + (((hb + i) & 255) << 8);
      float* dst = pre + c * 64 + i * 8;
      if (wx < 31) {
        *(float4*)dst = *(const float4*)(src + wb);
        *(float4*)(dst + 4) = *(const float4*)(src + wb + 4);
      } else {
#pragma unroll
        for (int j = 0; j < 8; ++j) dst[j] = src[(wb + j) & 255];
      }
    }
    // FIX: strided loop (288 > blockDim); previous `if (tid < 288)` left
    // wsm[256..287] (channels 28-31) uninitialized -> garbage qkv.
    for (int s = tid; s < 288; s += 256) {
      int c = s / 9, q = s - c * 9;
      wsm[s] = dw_w[(t3 * 192 + head * 32 + c) * 9 + q];
    }
    __syncthreads();

    // Depthwise 3x3 with per-window zero padding
    float* ob = (t3 == 0) ? qs : ((t3 == 1) ? ks : vs);
    const int stride = (t3 == 2) ? 64 : 68;
#pragma unroll
    for (int t = 0; t < 8; ++t) {
      int idx = (t << 8) + tid;
      int c = idx >> 6, pos = idx & 63, i = pos >> 3, j = pos & 7;
      const float* wp = wsm + c * 9;
      const float* p = pre + c * 64;
      float s = 0.f;
#pragma unroll
      for (int di = 0; di < 3; ++di) {
        int ii = i + di - 1;
        if ((unsigned)ii < 8u) {
#pragma unroll
          for (int dj = 0; dj < 3; ++dj) {
            int jc = j + dj - 1;
            if ((unsigned)jc < 8u) s += wp[di * 3 + dj] * p[ii * 8 + jc];
          }
        }
      }
      ob[c * stride + pos] = s;
    }
    __syncthreads();
  }

  // Row L2 norms
  {
    int r = tid >> 3, l = tid & 7;
    const float* qr = qs + r * 68 + l * 8;
    const float* kr = ks + r * 68 + l * 8;
    float sq = 0.f, sk = 0.f;
#pragma unroll
    for (int t = 0; t < 8; ++t) { sq += qr[t] * qr[t]; sk += kr[t] * kr[t]; }
#pragma unroll
    for (int m = 1; m < 8; m <<= 1) {
      sq += __shfl_xor_sync(0xffffffffu, sq, m);
      sk += __shfl_xor_sync(0xffffffffu, sk, m);
    }
    if (l == 0) {
      qsc[r] = 1.f / fmaxf(sqrtf(sq), 1e-12f);
      ksc[r] = 1.f / fmaxf(sqrtf(sk), 1e-12f);
    }
  }
  __syncthreads();

  // Logits (each thread 4 entries)
  {
    const float tv = temp[head];
    int rr = tid >> 3, cc0 = (tid & 7) * 4;
    const float* qr = qs + rr * 68;
    float d0 = 0.f, d1 = 0.f, d2 = 0.f, d3 = 0.f;
#pragma unroll
    for (int k = 0; k < 64; k += 4) {
      float4 qv = *(const float4*)(qr + k);
      float4 ka = *(const float4*)(ks + (cc0 + 0) * 68 + k);
      float4 kb = *(const float4*)(ks + (cc0 + 1) * 68 + k);
      float4 kc = *(const float4*)(ks + (cc0 + 2) * 68 + k);
      float4 kd = *(const float4*)(ks + (cc0 + 3) * 68 + k);
      d0 += qv.x * ka.x + qv.y * ka.y + qv.z * ka.z + qv.w * ka.w;
      d1 += qv.x * kb.x + qv.y * kb.y + qv.z * kb.z + qv.w * kb.w;
      d2 += qv.x * kc.x + qv.y * kc.y + qv.z * kc.z + qv.w * kc.w;
      d3 += qv.x * kd.x + qv.y * kd.y + qv.z * kd.z + qv.w * kd.w;
    }
    float qq = qsc[rr] * tv;
    attn[rr * 33 + cc0 + 0] = d0 * qq * ksc[cc0 + 0];
    attn[rr * 33 + cc0 + 1] = d1 * qq * ksc[cc0 + 1];
    attn[rr * 33 + cc0 + 2] = d2 * qq * ksc[cc0 + 2];
    attn[rr * 33 + cc0 + 3] = d3 * qq * ksc[cc0 + 3];
  }
  __syncthreads();

  // Softmax per row
  if (tid < 32) {
    float m = -1e30f;
#pragma unroll
    for (int c = 0; c < 32; ++c) m = fmaxf(m, attn[tid * 33 + c]);
    float s = 0.f;
#pragma unroll
    for (int c = 0; c < 32; ++c) {
      float e = __expf(attn[tid * 33 + c] - m);
      attn[tid * 33 + c] = e;
      s += e;
    }
    float inv = 1.f / s;
#pragma unroll
    for (int c = 0; c < 32; ++c) attn[tid * 33 + c] *= inv;
  }
  __syncthreads();

  // out = attn @ v, scatter to natural layout with inverse roll (+4)
  {
    int ro = tid >> 3, i = tid & 7, p0 = i * 8;
    float4 o0 = make_float4(0.f, 0.f, 0.f, 0.f);
    float4 o1 = make_float4(0.f, 0.f, 0.f, 0.f);
    const float* ar = attn + ro * 33;
#pragma unroll
    for (int c = 0; c < 32; ++c) {
      float a = ar[c];
      float4 v0 = *(const float4*)(vs + c * 64 + p0);
      float4 v1 = *(const float4*)(vs + c * 64 + p0 + 4);
      o0.x += a * v0.x; o0.y += a * v0.y; o0.z += a * v0.z; o0.w += a * v0.w;
      o1.x += a * v1.x; o1.y += a * v1.y; o1.z += a * v1.z; o1.w += a * v1.w;
    }
    int cch = head * 32 + ro;
    int hh = (wy * 8 + i + 4) & 255;
    float* dst = g_att + (long long)cch * 262144 + b * 65536 + (hh << 8);
    if (wx < 31) {
      *(float4*)(dst + wb) = o0;
      *(float4*)(dst + wb + 4) = o1;
    } else {
      float vv[8] = {o0.x, o0.y, o0.z, o0.w, o1.x, o1.y, o1.z, o1.w};
#pragma unroll
      for (int j = 0; j < 8; ++j) dst[(wb + j) & 255] = vv[j];
    }
  }
}

// ---------------------------------------------------------------------------
extern "C" void kernel_launch(void* const* d_in, const int* in_sizes, int n_in,
                              void* d_out, int out_size) {
  const float *x = nullptr, *qkvw = nullptr, *dww = nullptr, *projw = nullptr,
              *temp = nullptr;
  for (int i = 0; i < n_in; ++i) {
    switch (in_sizes[i]) {
      case 50331648: x = (const float*)d_in[i]; break;      // 4*192*256*256
      case 110592:   qkvw = (const float*)d_in[i]; break;   // 576*192
      case 5184:     dww = (const float*)d_in[i]; break;    // 576*9
      case 36864:    projw = (const float*)d_in[i]; break;  // 192*192
      case 6:        temp = (const float*)d_in[i]; break;   // heads
    }
  }

  float* gy;  cudaGetSymbolAddress((void**)&gy, g_y);
  float* ga;  cudaGetSymbolAddress((void**)&ga, g_att);

  // GEMM1: g_y[576, (b,pos)] = qkv_w @ x
  gemm_mma<<<dim3(2048, 5), 256>>>(qkvw, x, gy, 576, 65536LL, 12582912LL,
                                   262144LL, 65536LL);
  // dwconv + channel attention per (window, head)
  k2_dw_attn<<<dim3(4096, 6), 256>>>(dww, temp);
  // GEMM2: d_out[b, c, pos] = proj_w @ g_att
  gemm_mma<<<dim3(2048, 2), 256>>>(projw, ga, (float*)d_out, 192, 262144LL,
                                   65536LL, 65536LL, 12582912LL);
}

// round 12
// speedup vs baseline: 2.1847x; 2.1847x over previous
#include <cuda_runtime.h>
#include <cstdint>

// Scratch (module-scope device globals; no runtime allocation)
__device__ float g_y[576LL * 262144];    // qkv-linear output, [o][b][pos]
__device__ float g_att[192LL * 262144];  // attention output,  [c][b][pos]

// ---------------------------------------------------------------------------
__device__ __forceinline__ uint32_t smem_u32(const void* p) {
  uint32_t a;
  asm("{ .reg .u64 t; cvta.to.shared.u64 t, %1; cvt.u32.u64 %0, t; }"
      : "=r"(a) : "l"(p));
  return a;
}
#define CPA16(dst, src, sz) \
  asm volatile("cp.async.cg.shared.global [%0], [%1], 16, %2;" ::"r"(dst), "l"(src), "r"(sz))
#define CPA_COMMIT() asm volatile("cp.async.commit_group;")
#define CPA_WAIT(n) asm volatile("cp.async.wait_group %0;" ::"n"(n) : "memory")

__device__ __forceinline__ uint32_t f2tf(float f) {
  uint32_t u;
  asm("cvt.rna.tf32.f32 %0, %1;" : "=r"(u) : "f"(f));
  return u;
}
__device__ __forceinline__ void mma8(float* d, const uint32_t* a,
                                     const uint32_t* b) {
  asm volatile(
      "mma.sync.aligned.m16n8k8.row.col.f32.tf32.tf32.f32 "
      "{%0,%1,%2,%3},{%4,%5,%6,%7},{%8,%9},{%0,%1,%2,%3};"
      : "+f"(d[0]), "+f"(d[1]), "+f"(d[2]), "+f"(d[3])
      : "r"(a[0]), "r"(a[1]), "r"(a[2]), "r"(a[3]), "r"(b[0]), "r"(b[1]));
}

// ---------------------------------------------------------------------------
// Out[m, n] = sum_k W[m,k] * In[k, n],  n = b*65536 + pos (N-tile within one b)
// CTA tile 128x128, K=192 (12 chunks of 16, double-buffered cp.async).
// (unchanged from round 9)
// ---------------------------------------------------------------------------
__global__ void __launch_bounds__(256, 2) gemm_mma(
    const float* __restrict__ W, const float* __restrict__ In,
    float* __restrict__ Out, int Mvalid, long long ch_str, long long b_str,
    long long o_str, long long ob_str) {
  __shared__ __align__(16) float As[2][128 * 20];
  __shared__ __align__(16) float Bs[2][16 * 136];

  const int tid = threadIdx.x;
  const int warp = tid >> 5, lane = tid & 31, gid = lane >> 2, tig = lane & 3;
  const int wm = warp & 1, wn = warp >> 1;
  const int m0 = blockIdx.y << 7;
  const int n0 = blockIdx.x << 7;
  const int bb = n0 >> 16, pos0 = n0 & 65535;
  const float* inb = In + bb * b_str + pos0;
  const uint32_t sA = smem_u32(As), sB = smem_u32(Bs);

  float acc[4][4][4];
#pragma unroll
  for (int i = 0; i < 4; ++i)
#pragma unroll
    for (int j = 0; j < 4; ++j)
#pragma unroll
      for (int q = 0; q < 4; ++q) acc[i][j][q] = 0.f;

  auto loadA = [&](int buf, int kc) {
#pragma unroll
    for (int t = 0; t < 2; ++t) {
      int idx = (t << 8) + tid;
      int r = idx >> 2, q = idx & 3;
      int m = m0 + r;
      int valid = m < Mvalid;
      const float* src = W + (long long)(valid ? m : 0) * 192 + kc + (q << 2);
      uint32_t dst = sA + (uint32_t)(buf * 2560 + r * 20 + q * 4) * 4;
      CPA16(dst, src, valid ? 16 : 0);
    }
  };
  auto loadB = [&](int buf, int kc) {
#pragma unroll
    for (int t = 0; t < 2; ++t) {
      int idx = (t << 8) + tid;
      int r = idx >> 5, q = idx & 31;
      const float* src = inb + (long long)(kc + r) * ch_str + (q << 2);
      uint32_t dst = sB + (uint32_t)(buf * 2176 + r * 136 + q * 4) * 4;
      CPA16(dst, src, 16);
    }
  };

  auto compute = [&](int buf) {
    const float* A = As[buf];
    const float* B = Bs[buf];
#pragma unroll
    for (int kb = 0; kb < 2; ++kb) {
      const int kk = kb * 8;
      uint32_t af[4][4];
#pragma unroll
      for (int mf = 0; mf < 4; ++mf) {
        const float* ap = A + (wm * 64 + mf * 16 + gid) * 20 + kk + tig;
        af[mf][0] = f2tf(ap[0]);
        af[mf][1] = f2tf(ap[160]);
        af[mf][2] = f2tf(ap[4]);
        af[mf][3] = f2tf(ap[164]);
      }
      uint32_t bf[4][2];
#pragma unroll
      for (int nf = 0; nf < 4; ++nf) {
        const float* bp = B + (kk + tig) * 136 + wn * 32 + nf * 8 + gid;
        bf[nf][0] = f2tf(bp[0]);
        bf[nf][1] = f2tf(bp[544]);
      }
#pragma unroll
      for (int mf = 0; mf < 4; ++mf)
#pragma unroll
        for (int nf = 0; nf < 4; ++nf) mma8(acc[mf][nf], af[mf], bf[nf]);
    }
  };

  loadA(0, 0);
  loadB(0, 0);
  CPA_COMMIT();
#pragma unroll 1
  for (int i = 0; i < 12; ++i) {
    if (i + 1 < 12) {
      loadA((i + 1) & 1, (i + 1) * 16);
      loadB((i + 1) & 1, (i + 1) * 16);
      CPA_COMMIT();
      CPA_WAIT(1);
    } else {
      CPA_WAIT(0);
    }
    __syncthreads();
    compute(i & 1);
    __syncthreads();
  }

  // Epilogue: float2 stores (full 32B sectors per 4 consecutive lanes)
#pragma unroll
  for (int mf = 0; mf < 4; ++mf) {
    int mA = m0 + wm * 64 + mf * 16 + gid;
    int mB = mA + 8;
#pragma unroll
    for (int nf = 0; nf < 4; ++nf) {
      int c = pos0 + wn * 32 + nf * 8 + 2 * tig;
      if (mA < Mvalid)
        *(float2*)(Out + (long long)mA * o_str + bb * ob_str + c) =
            make_float2(acc[mf][nf][0], acc[mf][nf][1]);
      if (mB < Mvalid)
        *(float2*)(Out + (long long)mB * o_str + bb * ob_str + c) =
            make_float2(acc[mf][nf][2], acc[mf][nf][3]);
    }
  }
}

// ---------------------------------------------------------------------------
// k2: per (window, head): gather (roll + window) from g_y, depthwise 3x3,
// L2-norm channel attention, scatter to g_att (inverse roll).
// Rewritten: all 3 thirds gathered up-front (MLP), conflict-free smem access
// patterns in logits / norms / attn@v, 8-lane-parallel softmax, 5 barriers.
// ---------------------------------------------------------------------------
#define K2_SMEM 54656
__global__ void __launch_bounds__(256) k2_dw_attn(
    const float* __restrict__ dw_w, const float* __restrict__ temp) {
  extern __shared__ __align__(16) float smem[];
  float* pre = smem;            // 3 * 32 * 64 = 6144 floats
  float* qs = smem + 6144;      // 32 * 68
  float* ks = qs + 2176;        // 32 * 68
  float* vs = ks + 2176;        // 32 * 64
  float* attn = vs + 2048;      // 32 * 33
  float* qsc = attn + 1056;     // 32
  float* ksc = qsc + 32;        // 32
  float* wsm = attn;            // 864 dw weights, aliased (used pre-logits)

  const int tid = threadIdx.x, win = blockIdx.x, head = blockIdx.y;
  const int b = win >> 10, wy = (win >> 5) & 31, wx = win & 31;
  const int hb = wy * 8 + 4, wb = wx * 8 + 4;
  const int l = tid & 7;

  // Gather all 3 thirds: 96 channels x 64 positions (rolled window) from g_y
#pragma unroll
  for (int t3 = 0; t3 < 3; ++t3) {
    int c = tid >> 3, i = tid & 7;
    int cg = t3 * 192 + head * 32 + c;
    const float* src =
        g_y + (long long)cg * 262144 + b * 65536 + (((hb + i) & 255) << 8);
    float* dst = pre + t3 * 2048 + c * 64 + i * 8;
    if (wx < 31) {
      *(float4*)dst = *(const float4*)(src + wb);
      *(float4*)(dst + 4) = *(const float4*)(src + wb + 4);
    } else {
#pragma unroll
      for (int j = 0; j < 8; ++j) dst[j] = src[(wb + j) & 255];
    }
  }
  for (int s = tid; s < 864; s += 256) {
    int c96 = s / 9, q = s - c96 * 9;
    int third = c96 >> 5, cw = c96 & 31;
    wsm[s] = dw_w[(third * 192 + head * 32 + cw) * 9 + q];
  }
  __syncthreads();

  // Depthwise 3x3 with per-window zero padding -> qs/ks/vs
#pragma unroll 2
  for (int t = 0; t < 24; ++t) {
    int idx = (t << 8) + tid;
    int c96 = idx >> 6, pos = idx & 63, i = pos >> 3, j = pos & 7;
    int third = c96 >> 5, cw = c96 & 31;
    const float* wp = wsm + c96 * 9;
    const float* p = pre + c96 * 64;
    float s = 0.f;
#pragma unroll
    for (int di = 0; di < 3; ++di) {
      int ii = i + di - 1;
      if ((unsigned)ii < 8u) {
#pragma unroll
        for (int dj = 0; dj < 3; ++dj) {
          int jc = j + dj - 1;
          if ((unsigned)jc < 8u) s += wp[di * 3 + dj] * p[ii * 8 + jc];
        }
      }
    }
    float* ob = (third == 0) ? qs : ((third == 1) ? ks : vs);
    int stride = (third == 2) ? 64 : 68;
    ob[cw * stride + pos] = s;
  }
  __syncthreads();

  // Row L2 norms: 8 lanes per row, each lane two 16B chunks (conflict-free)
  {
    int r = tid >> 3;
    float4 qa = *(const float4*)&qs[r * 68 + l * 4];
    float4 qb = *(const float4*)&qs[r * 68 + 32 + l * 4];
    float4 ka = *(const float4*)&ks[r * 68 + l * 4];
    float4 kb = *(const float4*)&ks[r * 68 + 32 + l * 4];
    float sq = qa.x * qa.x + qa.y * qa.y + qa.z * qa.z + qa.w * qa.w +
               qb.x * qb.x + qb.y * qb.y + qb.z * qb.z + qb.w * qb.w;
    float sk = ka.x * ka.x + ka.y * ka.y + ka.z * ka.z + ka.w * ka.w +
               kb.x * kb.x + kb.y * kb.y + kb.z * kb.z + kb.w * kb.w;
#pragma unroll
    for (int m = 1; m < 8; m <<= 1) {
      sq += __shfl_xor_sync(0xffffffffu, sq, m);
      sk += __shfl_xor_sync(0xffffffffu, sk, m);
    }
    if (l == 0) {
      qsc[r] = 1.f / fmaxf(sqrtf(sq), 1e-12f);
      ksc[r] = 1.f / fmaxf(sqrtf(sk), 1e-12f);
    }
  }
  __syncthreads();

  // Logits: thread (rr, l) -> k-rows {l, l+8, l+16, l+24} (conflict-free: the
  // 8 lanes of a phase read 8 consecutive rows at pitch 68)
  {
    const float tv = temp[head];
    int rr = tid >> 3;
    const float* qr = qs + rr * 68;
    float d0 = 0.f, d1 = 0.f, d2 = 0.f, d3 = 0.f;
#pragma unroll
    for (int k = 0; k < 64; k += 4) {
      float4 qv = *(const float4*)(qr + k);
      float4 ka = *(const float4*)(ks + (l + 0) * 68 + k);
      float4 kb = *(const float4*)(ks + (l + 8) * 68 + k);
      float4 kc = *(const float4*)(ks + (l + 16) * 68 + k);
      float4 kd = *(const float4*)(ks + (l + 24) * 68 + k);
      d0 += qv.x * ka.x + qv.y * ka.y + qv.z * ka.z + qv.w * ka.w;
      d1 += qv.x * kb.x + qv.y * kb.y + qv.z * kb.z + qv.w * kb.w;
      d2 += qv.x * kc.x + qv.y * kc.y + qv.z * kc.z + qv.w * kc.w;
      d3 += qv.x * kd.x + qv.y * kd.y + qv.z * kd.z + qv.w * kd.w;
    }
    float qq = qsc[rr] * tv;
    attn[rr * 33 + l + 0] = d0 * qq * ksc[l + 0];
    attn[rr * 33 + l + 8] = d1 * qq * ksc[l + 8];
    attn[rr * 33 + l + 16] = d2 * qq * ksc[l + 16];
    attn[rr * 33 + l + 24] = d3 * qq * ksc[l + 24];
  }
  __syncthreads();

  // Softmax: 8 lanes per row, 4 entries each, shfl reduction within lane-octet
  {
    int r = tid >> 3;
    float v[4];
    float m = -1e30f;
#pragma unroll
    for (int q = 0; q < 4; ++q) {
      v[q] = attn[r * 33 + l + 8 * q];
      m = fmaxf(m, v[q]);
    }
#pragma unroll
    for (int mk = 1; mk < 8; mk <<= 1)
      m = fmaxf(m, __shfl_xor_sync(0xffffffffu, m, mk));
    float s = 0.f;
#pragma unroll
    for (int q = 0; q < 4; ++q) {
      v[q] = __expf(v[q] - m);
      s += v[q];
    }
#pragma unroll
    for (int mk = 1; mk < 8; mk <<= 1)
      s += __shfl_xor_sync(0xffffffffu, s, mk);
    float inv = 1.f / s;
#pragma unroll
    for (int q = 0; q < 4; ++q) attn[r * 33 + l + 8 * q] = v[q] * inv;
  }
  __syncthreads();

  // out = attn @ v: thread (ro, l) -> cols {l*4..l*4+3} and {32+l*4..+3}
  // (lanes 0-7 cover contiguous 128B -> conflict-free), scatter with +4 roll
  {
    int ro = tid >> 3;
    float4 o0 = make_float4(0.f, 0.f, 0.f, 0.f);
    float4 o1 = make_float4(0.f, 0.f, 0.f, 0.f);
    const float* ar = attn + ro * 33;
#pragma unroll
    for (int c = 0; c < 32; ++c) {
      float a = ar[c];
      float4 v0 = *(const float4*)(vs + c * 64 + l * 4);
      float4 v1 = *(const float4*)(vs + c * 64 + 32 + l * 4);
      o0.x += a * v0.x; o0.y += a * v0.y; o0.z += a * v0.z; o0.w += a * v0.w;
      o1.x += a * v1.x; o1.y += a * v1.y; o1.z += a * v1.z; o1.w += a * v1.w;
    }
    int cch = head * 32 + ro;
    int i0 = l >> 1, j0 = (l & 1) * 4;       // col0 = l*4  -> (i0, j0)
    int i1 = 4 + i0;                          // col1 = 32+l*4 -> (i1, j0)
    int hh0 = (wy * 8 + i0 + 4) & 255;
    int hh1 = (wy * 8 + i1 + 4) & 255;
    float* base = g_att + (long long)cch * 262144 + b * 65536;
    if (wx < 31) {
      *(float4*)(base + (hh0 << 8) + wb + j0) = o0;
      *(float4*)(base + (hh1 << 8) + wb + j0) = o1;
    } else {
      float va[4] = {o0.x, o0.y, o0.z, o0.w};
      float vb[4] = {o1.x, o1.y, o1.z, o1.w};
#pragma unroll
      for (int t = 0; t < 4; ++t) {
        base[(hh0 << 8) + ((wb + j0 + t) & 255)] = va[t];
        base[(hh1 << 8) + ((wb + j0 + t) & 255)] = vb[t];
      }
    }
  }
}

// ---------------------------------------------------------------------------
extern "C" void kernel_launch(void* const* d_in, const int* in_sizes, int n_in,
                              void* d_out, int out_size) {
  const float *x = nullptr, *qkvw = nullptr, *dww = nullptr, *projw = nullptr,
              *temp = nullptr;
  for (int i = 0; i < n_in; ++i) {
    switch (in_sizes[i]) {
      case 50331648: x = (const float*)d_in[i]; break;      // 4*192*256*256
      case 110592:   qkvw = (const float*)d_in[i]; break;   // 576*192
      case 5184:     dww = (const float*)d_in[i]; break;    // 576*9
      case 36864:    projw = (const float*)d_in[i]; break;  // 192*192
      case 6:        temp = (const float*)d_in[i]; break;   // heads
    }
  }

  cudaFuncSetAttribute(k2_dw_attn, cudaFuncAttributeMaxDynamicSharedMemorySize,
                       K2_SMEM);

  float* gy;  cudaGetSymbolAddress((void**)&gy, g_y);
  float* ga;  cudaGetSymbolAddress((void**)&ga, g_att);

  // GEMM1: g_y[576, (b,pos)] = qkv_w @ x
  gemm_mma<<<dim3(2048, 5), 256>>>(qkvw, x, gy, 576, 65536LL, 12582912LL,
                                   262144LL, 65536LL);
  // dwconv + channel attention per (window, head)
  k2_dw_attn<<<dim3(4096, 6), 256, K2_SMEM>>>(dww, temp);
  // GEMM2: d_out[b, c, pos] = proj_w @ g_att
  gemm_mma<<<dim3(2048, 2), 256>>>(projw, ga, (float*)d_out, 192, 262144LL,
                                   65536LL, 65536LL, 12582912LL);
}

// round 13
// speedup vs baseline: 2.9260x; 1.3393x over previous
#include <cuda_runtime.h>
#include <cstdint>

// Scratch (module-scope device globals; no runtime allocation)
__device__ float g_y[576LL * 262144];    // qkv-linear output, [o][b][pos]
__device__ float g_att[192LL * 262144];  // attention output,  [c][b][pos]

// ---------------------------------------------------------------------------
__device__ __forceinline__ uint32_t smem_u32(const void* p) {
  uint32_t a;
  asm("{ .reg .u64 t; cvta.to.shared.u64 t, %1; cvt.u32.u64 %0, t; }"
      : "=r"(a) : "l"(p));
  return a;
}
#define CPA16(dst, src, sz) \
  asm volatile("cp.async.cg.shared.global [%0], [%1], 16, %2;" ::"r"(dst), "l"(src), "r"(sz))
#define CPA_COMMIT() asm volatile("cp.async.commit_group;")
#define CPA_WAIT(n) asm volatile("cp.async.wait_group %0;" ::"n"(n) : "memory")

__device__ __forceinline__ uint32_t f2tf(float f) {
  uint32_t u;
  asm("cvt.rna.tf32.f32 %0, %1;" : "=r"(u) : "f"(f));
  return u;
}
__device__ __forceinline__ void mma8(float* d, const uint32_t* a,
                                     const uint32_t* b) {
  asm volatile(
      "mma.sync.aligned.m16n8k8.row.col.f32.tf32.tf32.f32 "
      "{%0,%1,%2,%3},{%4,%5,%6,%7},{%8,%9},{%0,%1,%2,%3};"
      : "+f"(d[0]), "+f"(d[1]), "+f"(d[2]), "+f"(d[3])
      : "r"(a[0]), "r"(a[1]), "r"(a[2]), "r"(a[3]), "r"(b[0]), "r"(b[1]));
}

// ---------------------------------------------------------------------------
// Out[m, n] = sum_k W[m,k] * In[k, n].  CTA tile 128x128, K=192.
// 3-stage cp.async pipeline (12 chunks of 16), one barrier per chunk.
// ---------------------------------------------------------------------------
#define GEMM_SMEM 56832
__global__ void __launch_bounds__(256, 2) gemm_mma(
    const float* __restrict__ W, const float* __restrict__ In,
    float* __restrict__ Out, int Mvalid, long long ch_str, long long b_str,
    long long o_str, long long ob_str) {
  extern __shared__ __align__(16) float dyn[];
  float* Asm = dyn;          // 3 * 2560 (128 x 20 per buf)
  float* Bsm = dyn + 7680;   // 3 * 2176 (16 x 136 per buf)

  const int tid = threadIdx.x;
  const int warp = tid >> 5, lane = tid & 31, gid = lane >> 2, tig = lane & 3;
  const int wm = warp & 1, wn = warp >> 1;
  const int m0 = blockIdx.y << 7;
  const int n0 = blockIdx.x << 7;
  const int bb = n0 >> 16, pos0 = n0 & 65535;
  const float* inb = In + bb * b_str + pos0;
  const uint32_t sA = smem_u32(Asm), sB = smem_u32(Bsm);

  float acc[4][4][4];
#pragma unroll
  for (int i = 0; i < 4; ++i)
#pragma unroll
    for (int j = 0; j < 4; ++j)
#pragma unroll
      for (int q = 0; q < 4; ++q) acc[i][j][q] = 0.f;

  auto loadA = [&](int buf, int kc) {
#pragma unroll
    for (int t = 0; t < 2; ++t) {
      int idx = (t << 8) + tid;
      int r = idx >> 2, q = idx & 3;
      int m = m0 + r;
      int valid = m < Mvalid;
      const float* src = W + (long long)(valid ? m : 0) * 192 + kc + (q << 2);
      uint32_t dst = sA + (uint32_t)(buf * 2560 + r * 20 + q * 4) * 4;
      CPA16(dst, src, valid ? 16 : 0);
    }
  };
  auto loadB = [&](int buf, int kc) {
#pragma unroll
    for (int t = 0; t < 2; ++t) {
      int idx = (t << 8) + tid;
      int r = idx >> 5, q = idx & 31;
      const float* src = inb + (long long)(kc + r) * ch_str + (q << 2);
      uint32_t dst = sB + (uint32_t)(buf * 2176 + r * 136 + q * 4) * 4;
      CPA16(dst, src, 16);
    }
  };

  auto compute = [&](int buf) {
    const float* A = Asm + buf * 2560;
    const float* B = Bsm + buf * 2176;
#pragma unroll
    for (int kb = 0; kb < 2; ++kb) {
      const int kk = kb * 8;
      uint32_t af[4][4];
#pragma unroll
      for (int mf = 0; mf < 4; ++mf) {
        const float* ap = A + (wm * 64 + mf * 16 + gid) * 20 + kk + tig;
        af[mf][0] = f2tf(ap[0]);
        af[mf][1] = f2tf(ap[160]);
        af[mf][2] = f2tf(ap[4]);
        af[mf][3] = f2tf(ap[164]);
      }
      uint32_t bf[4][2];
#pragma unroll
      for (int nf = 0; nf < 4; ++nf) {
        const float* bp = B + (kk + tig) * 136 + wn * 32 + nf * 8 + gid;
        bf[nf][0] = f2tf(bp[0]);
        bf[nf][1] = f2tf(bp[544]);
      }
#pragma unroll
      for (int mf = 0; mf < 4; ++mf)
#pragma unroll
        for (int nf = 0; nf < 4; ++nf) mma8(acc[mf][nf], af[mf], bf[nf]);
    }
  };

  loadA(0, 0);
  loadB(0, 0);
  CPA_COMMIT();
  loadA(1, 16);
  loadB(1, 16);
  CPA_COMMIT();
#pragma unroll 1
  for (int i = 0; i < 12; ++i) {
    if (i < 11) CPA_WAIT(1);
    else CPA_WAIT(0);
    __syncthreads();
    if (i + 2 < 12) {
      int nb = (i + 2) % 3;
      loadA(nb, (i + 2) * 16);
      loadB(nb, (i + 2) * 16);
      CPA_COMMIT();
    }
    compute(i % 3);
  }

  // Epilogue: float2 stores (full 32B sectors per 4 consecutive lanes)
#pragma unroll
  for (int mf = 0; mf < 4; ++mf) {
    int mA = m0 + wm * 64 + mf * 16 + gid;
    int mB = mA + 8;
#pragma unroll
    for (int nf = 0; nf < 4; ++nf) {
      int c = pos0 + wn * 32 + nf * 8 + 2 * tig;
      if (mA < Mvalid)
        *(float2*)(Out + (long long)mA * o_str + bb * ob_str + c) =
            make_float2(acc[mf][nf][0], acc[mf][nf][1]);
      if (mB < Mvalid)
        *(float2*)(Out + (long long)mB * o_str + bb * ob_str + c) =
            make_float2(acc[mf][nf][2], acc[mf][nf][3]);
    }
  }
}

// ---------------------------------------------------------------------------
// k2: per (window, head): gather (roll + window) from g_y into REGISTERS,
// depthwise 3x3 via warp shuffles (no smem), L2-norm channel attention with
// 2x2 / 2-row register blocking, scatter to g_att (inverse roll).
// ---------------------------------------------------------------------------
__global__ void __launch_bounds__(256) k2_dw_attn(
    const float* __restrict__ dw_w, const float* __restrict__ temp) {
  __shared__ __align__(16) float qs[32 * 68];
  __shared__ __align__(16) float ks[32 * 68];
  __shared__ __align__(16) float vs[32 * 64];
  __shared__ __align__(16) float attn[1056];   // 32*33; aliased for dw weights
  __shared__ float qsc[32], ksc[32];
  float* wsm = attn;  // 864 dw weights (read only before attn is written)

  const int tid = threadIdx.x, win = blockIdx.x, head = blockIdx.y;
  const int b = win >> 10, wy = (win >> 5) & 31, wx = win & 31;
  const int hb = wy * 8 + 4, wb = wx * 8 + 4;
  const int c = tid >> 3, i = tid & 7;

  // Stage 864 dw weights (strided; 864 > blockDim)
  for (int s = tid; s < 864; s += 256) {
    int c96 = s / 9, q = s - c96 * 9;
    int third = c96 >> 5, cw = c96 & 31;
    wsm[s] = dw_w[(third * 192 + head * 32 + cw) * 9 + q];
  }

  // Gather: thread (c,i) holds window row i (8 floats) of channel c
  float xa[8], xb[8];
  auto gather = [&](int t3, float* x) {
    int cg = t3 * 192 + head * 32 + c;
    const float* src =
        g_y + (long long)cg * 262144 + b * 65536 + (((hb + i) & 255) << 8);
    if (wx < 31) {
      float4 u = *(const float4*)(src + wb);
      float4 v = *(const float4*)(src + wb + 4);
      x[0] = u.x; x[1] = u.y; x[2] = u.z; x[3] = u.w;
      x[4] = v.x; x[5] = v.y; x[6] = v.z; x[7] = v.w;
    } else {
#pragma unroll
      for (int j = 0; j < 8; ++j) x[j] = src[(wb + j) & 255];
    }
  };
  gather(0, xa);
  __syncthreads();  // wsm ready

  // Depthwise 3x3: vertical neighbors via shfl within octet, zero-padded
#pragma unroll
  for (int t3 = 0; t3 < 3; ++t3) {
    if (t3 < 2) gather(t3 + 1, xb);  // prefetch next third
    float pv[8], nx[8];
#pragma unroll
    for (int j = 0; j < 8; ++j) {
      pv[j] = __shfl_up_sync(0xffffffffu, xa[j], 1);
      nx[j] = __shfl_down_sync(0xffffffffu, xa[j], 1);
    }
    if (i == 0)
#pragma unroll
      for (int j = 0; j < 8; ++j) pv[j] = 0.f;
    if (i == 7)
#pragma unroll
      for (int j = 0; j < 8; ++j) nx[j] = 0.f;
    const float* wp = wsm + (t3 * 32 + c) * 9;
    float w0 = wp[0], w1 = wp[1], w2 = wp[2], w3 = wp[3], w4 = wp[4],
          w5 = wp[5], w6 = wp[6], w7 = wp[7], w8 = wp[8];
    float out[8];
#pragma unroll
    for (int j = 0; j < 8; ++j) {
      float s = w1 * pv[j] + w4 * xa[j] + w7 * nx[j];
      if (j > 0) s += w0 * pv[j - 1] + w3 * xa[j - 1] + w6 * nx[j - 1];
      if (j < 7) s += w2 * pv[j + 1] + w5 * xa[j + 1] + w8 * nx[j + 1];
      out[j] = s;
    }
    float* ob = (t3 == 0) ? qs : ((t3 == 1) ? ks : vs);
    int stride = (t3 == 2) ? 64 : 68;
    *(float4*)&ob[c * stride + i * 8] =
        make_float4(out[0], out[1], out[2], out[3]);
    *(float4*)&ob[c * stride + i * 8 + 4] =
        make_float4(out[4], out[5], out[6], out[7]);
    if (t3 < 2) {
#pragma unroll
      for (int j = 0; j < 8; ++j) xa[j] = xb[j];
    }
  }
  __syncthreads();

  // Row L2 norms: 8 lanes per row, two 16B chunks each (conflict-free)
  {
    float4 qa = *(const float4*)&qs[c * 68 + i * 4];
    float4 qb = *(const float4*)&qs[c * 68 + 32 + i * 4];
    float4 ka = *(const float4*)&ks[c * 68 + i * 4];
    float4 kb = *(const float4*)&ks[c * 68 + 32 + i * 4];
    float sq = qa.x * qa.x + qa.y * qa.y + qa.z * qa.z + qa.w * qa.w +
               qb.x * qb.x + qb.y * qb.y + qb.z * qb.z + qb.w * qb.w;
    float sk = ka.x * ka.x + ka.y * ka.y + ka.z * ka.z + ka.w * ka.w +
               kb.x * kb.x + kb.y * kb.y + kb.z * kb.z + kb.w * kb.w;
#pragma unroll
    for (int m = 1; m < 8; m <<= 1) {
      sq += __shfl_xor_sync(0xffffffffu, sq, m);
      sk += __shfl_xor_sync(0xffffffffu, sk, m);
    }
    if (i == 0) {
      qsc[c] = 1.f / fmaxf(sqrtf(sq), 1e-12f);
      ksc[c] = 1.f / fmaxf(sqrtf(sk), 1e-12f);
    }
  }
  __syncthreads();

  // Logits, 2x2 blocked: thread (rr,cc) -> rows {rr,rr+16} x cols {cc,cc+16}
  {
    const float tv = temp[head];
    int rr = tid >> 4, cc = tid & 15;
    const float* q0 = qs + rr * 68;
    const float* q1 = qs + (rr + 16) * 68;
    const float* k0 = ks + cc * 68;
    const float* k1 = ks + (cc + 16) * 68;
    float d00 = 0.f, d01 = 0.f, d10 = 0.f, d11 = 0.f;
#pragma unroll
    for (int k = 0; k < 64; k += 4) {
      float4 qa = *(const float4*)(q0 + k);
      float4 qb = *(const float4*)(q1 + k);
      float4 ka = *(const float4*)(k0 + k);
      float4 kb = *(const float4*)(k1 + k);
      d00 += qa.x * ka.x + qa.y * ka.y + qa.z * ka.z + qa.w * ka.w;
      d01 += qa.x * kb.x + qa.y * kb.y + qa.z * kb.z + qa.w * kb.w;
      d10 += qb.x * ka.x + qb.y * ka.y + qb.z * ka.z + qb.w * ka.w;
      d11 += qb.x * kb.x + qb.y * kb.y + qb.z * kb.z + qb.w * kb.w;
    }
    float s0 = qsc[rr] * tv, s1 = qsc[rr + 16] * tv;
    attn[rr * 33 + cc] = d00 * s0 * ksc[cc];
    attn[rr * 33 + cc + 16] = d01 * s0 * ksc[cc + 16];
    attn[(rr + 16) * 33 + cc] = d10 * s1 * ksc[cc];
    attn[(rr + 16) * 33 + cc + 16] = d11 * s1 * ksc[cc + 16];
  }
  __syncthreads();

  // Softmax: 8 lanes per row, 4 entries each
  {
    int r = tid >> 3, l = tid & 7;
    float v[4];
    float m = -1e30f;
#pragma unroll
    for (int q = 0; q < 4; ++q) {
      v[q] = attn[r * 33 + l + 8 * q];
      m = fmaxf(m, v[q]);
    }
#pragma unroll
    for (int mk = 1; mk < 8; mk <<= 1)
      m = fmaxf(m, __shfl_xor_sync(0xffffffffu, m, mk));
    float s = 0.f;
#pragma unroll
    for (int q = 0; q < 4; ++q) {
      v[q] = __expf(v[q] - m);
      s += v[q];
    }
#pragma unroll
    for (int mk = 1; mk < 8; mk <<= 1)
      s += __shfl_xor_sync(0xffffffffu, s, mk);
    float inv = 1.f / s;
#pragma unroll
    for (int q = 0; q < 4; ++q) attn[r * 33 + l + 8 * q] = v[q] * inv;
  }
  __syncthreads();

  // out = attn @ v, 2-row blocked: rows {ro,ro+16} share each v float4
  {
    int ro = tid >> 4, c4 = (tid & 15) * 4;
    float4 o0 = make_float4(0.f, 0.f, 0.f, 0.f);
    float4 o1 = make_float4(0.f, 0.f, 0.f, 0.f);
    const float* a0 = attn + ro * 33;
    const float* a1 = attn + (ro + 16) * 33;
#pragma unroll
    for (int cc = 0; cc < 32; ++cc) {
      float4 v4 = *(const float4*)&vs[cc * 64 + c4];
      float s0 = a0[cc], s1 = a1[cc];
      o0.x += s0 * v4.x; o0.y += s0 * v4.y; o0.z += s0 * v4.z; o0.w += s0 * v4.w;
      o1.x += s1 * v4.x; o1.y += s1 * v4.y; o1.z += s1 * v4.z; o1.w += s1 * v4.w;
    }
    int i0 = c4 >> 3, j0 = c4 & 7;  // j0 in {0,4}
    int hh = (wy * 8 + i0 + 4) & 255;
    long long boff = b * 65536 + ((long long)hh << 8);
    float* d0 = g_att + (long long)(head * 32 + ro) * 262144 + boff;
    float* d1 = g_att + (long long)(head * 32 + ro + 16) * 262144 + boff;
    if (wx < 31) {
      *(float4*)(d0 + wb + j0) = o0;
      *(float4*)(d1 + wb + j0) = o1;
    } else {
      float va[4] = {o0.x, o0.y, o0.z, o0.w};
      float vb[4] = {o1.x, o1.y, o1.z, o1.w};
#pragma unroll
      for (int t = 0; t < 4; ++t) {
        d0[(wb + j0 + t) & 255] = va[t];
        d1[(wb + j0 + t) & 255] = vb[t];
      }
    }
  }
}

// ---------------------------------------------------------------------------
extern "C" void kernel_launch(void* const* d_in, const int* in_sizes, int n_in,
                              void* d_out, int out_size) {
  const float *x = nullptr, *qkvw = nullptr, *dww = nullptr, *projw = nullptr,
              *temp = nullptr;
  for (int i = 0; i < n_in; ++i) {
    switch (in_sizes[i]) {
      case 50331648: x = (const float*)d_in[i]; break;      // 4*192*256*256
      case 110592:   qkvw = (const float*)d_in[i]; break;   // 576*192
      case 5184:     dww = (const float*)d_in[i]; break;    // 576*9
      case 36864:    projw = (const float*)d_in[i]; break;  // 192*192
      case 6:        temp = (const float*)d_in[i]; break;   // heads
    }
  }

  cudaFuncSetAttribute(gemm_mma, cudaFuncAttributeMaxDynamicSharedMemorySize,
                       GEMM_SMEM);

  float* gy;  cudaGetSymbolAddress((void**)&gy, g_y);
  float* ga;  cudaGetSymbolAddress((void**)&ga, g_att);

  // GEMM1: g_y[576, (b,pos)] = qkv_w @ x
  gemm_mma<<<dim3(2048, 5), 256, GEMM_SMEM>>>(qkvw, x, gy, 576, 65536LL,
                                              12582912LL, 262144LL, 65536LL);
  // dwconv + channel attention per (window, head)
  k2_dw_attn<<<dim3(4096, 6), 256>>>(dww, temp);
  // GEMM2: d_out[b, c, pos] = proj_w @ g_att
  gemm_mma<<<dim3(2048, 2), 256, GEMM_SMEM>>>(projw, ga, (float*)d_out, 192,
                                              262144LL, 65536LL, 65536LL,
                                              12582912LL);
}